// round 2
// baseline (speedup 1.0000x reference)
#include <cuda_runtime.h>
#include <math.h>

// Problem constants
#define BB   2
#define LL   2048
#define HH   1024
#define NH   16
#define HD   64
#define MM   (BB*LL)   // 4096 rows
#define LN_EPS 1e-12f

// Scratch (static __device__ globals: allowed; no runtime allocation)
__device__ float g_Q[MM*HH];
__device__ float g_K[MM*HH];
__device__ float g_V[MM*HH];
__device__ float g_att[MM*HH];
__device__ float g_proj[MM*HH];

// ---------------------------------------------------------------------------
// GEMM: C[M,N] = A[M,K] @ W[K,N] + bias[N] (+ residual[M,N])
// 128x128 tile, BK=16, 256 threads, 8x8 per thread
// ---------------------------------------------------------------------------
__global__ __launch_bounds__(256) void gemm_bias_kernel(
    const float* __restrict__ A, const float* __restrict__ W,
    const float* __restrict__ bias, const float* __restrict__ residual,
    float* __restrict__ C, int M, int N, int K)
{
    __shared__ float As[16][128];   // transposed: As[k][m]
    __shared__ float Bs[16][128];   // Bs[k][n]

    const int tid = threadIdx.x;
    const int tn  = tid & 15;       // 0..15 -> cols tn*8
    const int tm  = tid >> 4;       // 0..15 -> rows tm*8
    const int m0  = blockIdx.y * 128;
    const int n0  = blockIdx.x * 128;

    float acc[8][8];
    #pragma unroll
    for (int i = 0; i < 8; i++)
        #pragma unroll
        for (int j = 0; j < 8; j++) acc[i][j] = 0.f;

    for (int k0 = 0; k0 < K; k0 += 16) {
        // Load A tile (128 rows x 16 cols): 512 float4s, 2 per thread
        #pragma unroll
        for (int t = 0; t < 2; t++) {
            int f   = tid * 2 + t;
            int row = f >> 2;             // 0..127
            int kc  = (f & 3) * 4;        // 0,4,8,12
            float4 v = *(const float4*)(A + (size_t)(m0 + row) * K + k0 + kc);
            As[kc + 0][row] = v.x;
            As[kc + 1][row] = v.y;
            As[kc + 2][row] = v.z;
            As[kc + 3][row] = v.w;
        }
        // Load B tile (16 rows x 128 cols): 512 float4s, 2 per thread
        #pragma unroll
        for (int t = 0; t < 2; t++) {
            int f = tid * 2 + t;
            int r = f >> 5;               // 0..15
            int c = (f & 31) * 4;         // 0..124
            *(float4*)&Bs[r][c] = *(const float4*)(W + (size_t)(k0 + r) * N + n0 + c);
        }
        __syncthreads();

        #pragma unroll
        for (int k = 0; k < 16; k++) {
            float a[8], b[8];
            *(float4*)&a[0] = *(float4*)&As[k][tm * 8];
            *(float4*)&a[4] = *(float4*)&As[k][tm * 8 + 4];
            *(float4*)&b[0] = *(float4*)&Bs[k][tn * 8];
            *(float4*)&b[4] = *(float4*)&Bs[k][tn * 8 + 4];
            #pragma unroll
            for (int i = 0; i < 8; i++)
                #pragma unroll
                for (int j = 0; j < 8; j++)
                    acc[i][j] = fmaf(a[i], b[j], acc[i][j]);
        }
        __syncthreads();
    }

    // Epilogue
    float bb[8];
    #pragma unroll
    for (int j = 0; j < 8; j++) bb[j] = bias[n0 + tn * 8 + j];

    #pragma unroll
    for (int i = 0; i < 8; i++) {
        int row = m0 + tm * 8 + i;
        size_t base = (size_t)row * N + n0 + tn * 8;
        float out[8];
        #pragma unroll
        for (int j = 0; j < 8; j++) out[j] = acc[i][j] + bb[j];
        if (residual) {
            float4 r0 = *(const float4*)(residual + base);
            float4 r1 = *(const float4*)(residual + base + 4);
            out[0] += r0.x; out[1] += r0.y; out[2] += r0.z; out[3] += r0.w;
            out[4] += r1.x; out[5] += r1.y; out[6] += r1.z; out[7] += r1.w;
        }
        *(float4*)(C + base)     = make_float4(out[0], out[1], out[2], out[3]);
        *(float4*)(C + base + 4) = make_float4(out[4], out[5], out[6], out[7]);
    }
}

// ---------------------------------------------------------------------------
// Flash attention (note role swap per reference):
//   scores  = Q @ V^T * 0.25 + mask
//   weights = softmax(scores)
//   out     = weights @ K
// Tile: TQ=32 query rows, TK=64 keys per iteration, head dim 64, 128 threads.
// Thread (tm=tid/16 in 0..7, tn=tid%16): 4x4 micro-tiles.
// Row-softmax reductions across 16-lane groups (aligned to warp halves).
// ---------------------------------------------------------------------------
#define TQ 32
#define TK 64

__global__ __launch_bounds__(128) void flash_attn_kernel(
    const float* __restrict__ Q, const float* __restrict__ Kmat,
    const float* __restrict__ Vmat, const float* __restrict__ mask,
    float* __restrict__ Out)
{
    __shared__ float Qs[TQ][64];        // [qrow][k]
    __shared__ float KVs[TK][68];       // [key][dim], padded
    __shared__ float Ps[TQ][64];        // probabilities
    __shared__ float maskS[TK];

    const int tid = threadIdx.x;
    const int tn  = tid & 15;           // 0..15 -> dims/cols tn*4
    const int tm  = tid >> 4;           // 0..7  -> rows tm*4
    const int qt  = blockIdx.x;         // query tile
    const int h   = blockIdx.y;         // head
    const int b   = blockIdx.z;         // batch

    const int row0 = b * LL + qt * TQ;
    const int col0 = h * HD;

    // Load Q tile: TQ*64/4 = 512 float4s over 128 threads
    for (int t = tid; t < TQ * 16; t += 128) {
        int r = t >> 4, c = (t & 15) * 4;
        *(float4*)&Qs[r][c] = *(const float4*)(Q + (size_t)(row0 + r) * HH + col0 + c);
    }

    float o[4][4];
    float mrow[4], lrow[4];
    #pragma unroll
    for (int i = 0; i < 4; i++) {
        mrow[i] = -1e30f; lrow[i] = 0.f;
        #pragma unroll
        for (int j = 0; j < 4; j++) o[i][j] = 0.f;
    }
    __syncthreads();

    for (int kb = 0; kb < LL / TK; kb++) {
        const int krow0 = b * LL + kb * TK;

        // Load V tile (acts as "key" matrix for scores)
        for (int t = tid; t < TK * 16; t += 128) {
            int r = t >> 4, c = (t & 15) * 4;
            *(float4*)&KVs[r][c] = *(const float4*)(Vmat + (size_t)(krow0 + r) * HH + col0 + c);
        }
        if (tid < TK) maskS[tid] = mask[b * LL + kb * TK + tid];
        __syncthreads();

        // S = Q @ V^T
        float s[4][4];
        #pragma unroll
        for (int i = 0; i < 4; i++)
            #pragma unroll
            for (int j = 0; j < 4; j++) s[i][j] = 0.f;

        #pragma unroll
        for (int k = 0; k < 64; k += 4) {
            float4 q4[4], kv4[4];
            #pragma unroll
            for (int i = 0; i < 4; i++) q4[i]  = *(float4*)&Qs[tm * 4 + i][k];
            #pragma unroll
            for (int j = 0; j < 4; j++) kv4[j] = *(float4*)&KVs[tn * 4 + j][k];
            #pragma unroll
            for (int i = 0; i < 4; i++)
                #pragma unroll
                for (int j = 0; j < 4; j++)
                    s[i][j] += q4[i].x * kv4[j].x + q4[i].y * kv4[j].y
                             + q4[i].z * kv4[j].z + q4[i].w * kv4[j].w;
        }

        // scale + mask; online softmax per row (16-lane groups)
        #pragma unroll
        for (int i = 0; i < 4; i++) {
            #pragma unroll
            for (int j = 0; j < 4; j++)
                s[i][j] = s[i][j] * 0.25f + maskS[tn * 4 + j];

            float mx = fmaxf(fmaxf(s[i][0], s[i][1]), fmaxf(s[i][2], s[i][3]));
            #pragma unroll
            for (int off = 8; off; off >>= 1)
                mx = fmaxf(mx, __shfl_xor_sync(0xffffffffu, mx, off, 16));

            float mnew = fmaxf(mrow[i], mx);
            float corr = __expf(mrow[i] - mnew);
            float rs = 0.f;
            #pragma unroll
            for (int j = 0; j < 4; j++) {
                s[i][j] = __expf(s[i][j] - mnew);
                rs += s[i][j];
            }
            #pragma unroll
            for (int off = 8; off; off >>= 1)
                rs += __shfl_xor_sync(0xffffffffu, rs, off, 16);

            lrow[i] = lrow[i] * corr + rs;
            mrow[i] = mnew;
            #pragma unroll
            for (int j = 0; j < 4; j++) o[i][j] *= corr;

            *(float4*)&Ps[tm * 4 + i][tn * 4] = make_float4(s[i][0], s[i][1], s[i][2], s[i][3]);
        }
        __syncthreads();

        // Load K tile (acts as "value" matrix), overwriting KVs
        for (int t = tid; t < TK * 16; t += 128) {
            int r = t >> 4, c = (t & 15) * 4;
            *(float4*)&KVs[r][c] = *(const float4*)(Kmat + (size_t)(krow0 + r) * HH + col0 + c);
        }
        __syncthreads();

        // O += P @ K
        #pragma unroll
        for (int c = 0; c < 64; c += 4) {
            float4 p4[4], kk4[4];
            #pragma unroll
            for (int i = 0; i < 4; i++)  p4[i]  = *(float4*)&Ps[tm * 4 + i][c];
            #pragma unroll
            for (int cc = 0; cc < 4; cc++) kk4[cc] = *(float4*)&KVs[c + cc][tn * 4];
            #pragma unroll
            for (int i = 0; i < 4; i++) {
                o[i][0] += p4[i].x * kk4[0].x + p4[i].y * kk4[1].x + p4[i].z * kk4[2].x + p4[i].w * kk4[3].x;
                o[i][1] += p4[i].x * kk4[0].y + p4[i].y * kk4[1].y + p4[i].z * kk4[2].y + p4[i].w * kk4[3].y;
                o[i][2] += p4[i].x * kk4[0].z + p4[i].y * kk4[1].z + p4[i].z * kk4[2].z + p4[i].w * kk4[3].z;
                o[i][3] += p4[i].x * kk4[0].w + p4[i].y * kk4[1].w + p4[i].z * kk4[2].w + p4[i].w * kk4[3].w;
            }
        }
        __syncthreads();
    }

    // Normalize and write
    #pragma unroll
    for (int i = 0; i < 4; i++) {
        float inv = 1.f / lrow[i];
        int row = row0 + tm * 4 + i;
        *(float4*)(Out + (size_t)row * HH + col0 + tn * 4) =
            make_float4(o[i][0] * inv, o[i][1] * inv, o[i][2] * inv, o[i][3] * inv);
    }
}

// ---------------------------------------------------------------------------
// Row LayerNorm: one block per row of 1024, 256 threads (4 elems each)
// ---------------------------------------------------------------------------
__global__ __launch_bounds__(256) void ln_kernel(
    const float* __restrict__ X, const float* __restrict__ gamma,
    const float* __restrict__ beta, float* __restrict__ Y)
{
    __shared__ float sred[8];
    const int r = blockIdx.x;
    const int tid = threadIdx.x;
    const float* x = X + (size_t)r * HH;

    float4 v = *(const float4*)(x + tid * 4);

    float s = v.x + v.y + v.z + v.w;
    #pragma unroll
    for (int off = 16; off; off >>= 1) s += __shfl_xor_sync(0xffffffffu, s, off);
    if ((tid & 31) == 0) sred[tid >> 5] = s;
    __syncthreads();
    float tot = 0.f;
    #pragma unroll
    for (int i = 0; i < 8; i++) tot += sred[i];
    const float mu = tot * (1.f / HH);
    __syncthreads();

    float d0 = v.x - mu, d1 = v.y - mu, d2 = v.z - mu, d3 = v.w - mu;
    float sq = d0 * d0 + d1 * d1 + d2 * d2 + d3 * d3;
    #pragma unroll
    for (int off = 16; off; off >>= 1) sq += __shfl_xor_sync(0xffffffffu, sq, off);
    if ((tid & 31) == 0) sred[tid >> 5] = sq;
    __syncthreads();
    float vtot = 0.f;
    #pragma unroll
    for (int i = 0; i < 8; i++) vtot += sred[i];
    const float var = vtot * (1.f / HH);
    const float inv = rsqrtf(var + LN_EPS);

    float4 g  = *(const float4*)(gamma + tid * 4);
    float4 be = *(const float4*)(beta  + tid * 4);
    *(float4*)(Y + (size_t)r * HH + tid * 4) = make_float4(
        d0 * inv * g.x + be.x, d1 * inv * g.y + be.y,
        d2 * inv * g.z + be.z, d3 * inv * g.w + be.w);
}

// ---------------------------------------------------------------------------
// Launch
// Inputs (metadata order): embeddings, mask, Wq, bq, Wk, bk, Wv, bv,
//                          Wo, bo, ln_gamma, ln_beta
// ---------------------------------------------------------------------------
extern "C" void kernel_launch(void* const* d_in, const int* in_sizes, int n_in,
                              void* d_out, int out_size)
{
    const float* emb   = (const float*)d_in[0];
    const float* mask  = (const float*)d_in[1];
    const float* Wq    = (const float*)d_in[2];
    const float* bq    = (const float*)d_in[3];
    const float* Wk    = (const float*)d_in[4];
    const float* bk    = (const float*)d_in[5];
    const float* Wv    = (const float*)d_in[6];
    const float* bv    = (const float*)d_in[7];
    const float* Wo    = (const float*)d_in[8];
    const float* bo    = (const float*)d_in[9];
    const float* gamma = (const float*)d_in[10];
    const float* beta  = (const float*)d_in[11];
    float* out = (float*)d_out;

    float *Qp, *Kp, *Vp, *Ap, *Pp;
    cudaGetSymbolAddress((void**)&Qp, g_Q);
    cudaGetSymbolAddress((void**)&Kp, g_K);
    cudaGetSymbolAddress((void**)&Vp, g_V);
    cudaGetSymbolAddress((void**)&Ap, g_att);
    cudaGetSymbolAddress((void**)&Pp, g_proj);

    dim3 ggrid(HH / 128, MM / 128);   // (8, 32)
    gemm_bias_kernel<<<ggrid, 256>>>(emb, Wq, bq, nullptr, Qp, MM, HH, HH);
    gemm_bias_kernel<<<ggrid, 256>>>(emb, Wk, bk, nullptr, Kp, MM, HH, HH);
    gemm_bias_kernel<<<ggrid, 256>>>(emb, Wv, bv, nullptr, Vp, MM, HH, HH);

    dim3 agrid(LL / TQ, NH, BB);      // (64, 16, 2)
    flash_attn_kernel<<<agrid, 128>>>(Qp, Kp, Vp, mask, Ap);

    gemm_bias_kernel<<<ggrid, 256>>>(Ap, Wo, bo, emb, Pp, MM, HH, HH);

    ln_kernel<<<MM, 256>>>(Pp, gamma, beta, out);
}

// round 8
// speedup vs baseline: 1.3132x; 1.3132x over previous
#include <cuda_runtime.h>
#include <math.h>
#include <stdint.h>

// Problem constants
#define BB   2
#define LL   2048
#define HH   1024
#define NH   16
#define HD   64
#define MM   (BB*LL)   // 4096 rows
#define LN_EPS 1e-12f

// Scratch (static __device__ globals: allowed; no runtime allocation)
__device__ float g_Q[MM*HH];
__device__ float g_K[MM*HH];
__device__ float g_V[MM*HH];
__device__ float g_att[MM*HH];
__device__ float g_proj[MM*HH];

__device__ __forceinline__ uint32_t cvt_tf32(float x) {
    uint32_t r; asm("cvt.rna.tf32.f32 %0, %1;" : "=r"(r) : "f"(x)); return r;
}

// Warp-level tensor-core MMA (arch-generic, works on sm_103 base target):
// D[16x8] += A[16x8] * B[8x8], tf32 inputs, f32 accumulate.
__device__ __forceinline__ void mma16n8k8(float c[4], const uint32_t a[4],
                                          const uint32_t b[2]) {
    asm volatile(
        "mma.sync.aligned.m16n8k8.row.col.f32.tf32.tf32.f32 "
        "{%0,%1,%2,%3}, {%4,%5,%6,%7}, {%8,%9}, {%0,%1,%2,%3};"
        : "+f"(c[0]), "+f"(c[1]), "+f"(c[2]), "+f"(c[3])
        : "r"(a[0]), "r"(a[1]), "r"(a[2]), "r"(a[3]),
          "r"(b[0]), "r"(b[1]));
}

// ===========================================================================
// tf32 warp-MMA GEMM: C[M,N] = A[M,K] @ W[K,N] + bias (+ residual)
// CTA tile 128x128, BK=32, 256 threads (8 warps, 4x2), warp tile 32x64.
// ===========================================================================
#define BK 32
#define SA_PAD 36   // bank map (4g + c): conflict-free
#define SB_PAD 136  // bank map (8t + g): conflict-free

__global__ __launch_bounds__(256) void gemm_mma_kernel(
    const float* __restrict__ A, const float* __restrict__ W,
    const float* __restrict__ bias, const float* __restrict__ residual,
    float* __restrict__ C)
{
    __shared__ float sA[128][SA_PAD];
    __shared__ float sB[BK][SB_PAD];

    const int tid = threadIdx.x;
    const int lid = tid & 31;
    const int wid = tid >> 5;
    const int wm  = (wid >> 1) * 32;    // warp M offset: 0,32,64,96
    const int wn  = (wid & 1) * 64;     // warp N offset: 0,64
    const int g   = lid >> 2;           // group 0..7
    const int t   = lid & 3;            // thread-in-group 0..3

    const int m0 = blockIdx.y * 128;
    const int n0 = blockIdx.x * 128;

    float acc[2][8][4];
    #pragma unroll
    for (int i = 0; i < 2; i++)
        #pragma unroll
        for (int j = 0; j < 8; j++)
            #pragma unroll
            for (int q = 0; q < 4; q++) acc[i][j][q] = 0.f;

    float4 ra[4], rb[4];

    // Load tile 0
    #pragma unroll
    for (int i = 0; i < 4; i++) {
        int f = i * 256 + tid;
        int r = f >> 3, c = f & 7;                 // A: 128 rows x 8 float4
        ra[i] = *(const float4*)(A + (size_t)(m0 + r) * HH + c * 4);
        int rB = f >> 5, cB = f & 31;              // B: 32 rows x 32 float4
        rb[i] = *(const float4*)(W + (size_t)rB * HH + n0 + cB * 4);
    }

    for (int kc = 0; kc < HH / BK; kc++) {
        // Store staged regs to smem (convert to tf32)
        #pragma unroll
        for (int i = 0; i < 4; i++) {
            int f = i * 256 + tid;
            int r = f >> 3, c = f & 7;
            float* pa = &sA[r][c * 4];
            pa[0] = __uint_as_float(cvt_tf32(ra[i].x));
            pa[1] = __uint_as_float(cvt_tf32(ra[i].y));
            pa[2] = __uint_as_float(cvt_tf32(ra[i].z));
            pa[3] = __uint_as_float(cvt_tf32(ra[i].w));
            int rB = f >> 5, cB = f & 31;
            float* pb = &sB[rB][cB * 4];
            pb[0] = __uint_as_float(cvt_tf32(rb[i].x));
            pb[1] = __uint_as_float(cvt_tf32(rb[i].y));
            pb[2] = __uint_as_float(cvt_tf32(rb[i].z));
            pb[3] = __uint_as_float(cvt_tf32(rb[i].w));
        }
        __syncthreads();

        // Prefetch next tile (LDGs overlap with MMA compute below)
        if (kc + 1 < HH / BK) {
            int k0 = (kc + 1) * BK;
            #pragma unroll
            for (int i = 0; i < 4; i++) {
                int f = i * 256 + tid;
                int r = f >> 3, c = f & 7;
                ra[i] = *(const float4*)(A + (size_t)(m0 + r) * HH + k0 + c * 4);
                int rB = f >> 5, cB = f & 31;
                rb[i] = *(const float4*)(W + (size_t)(k0 + rB) * HH + n0 + cB * 4);
            }
        }

        // Compute: 4 k-steps of 8
        #pragma unroll
        for (int kk = 0; kk < 4; kk++) {
            uint32_t afr[2][4];
            #pragma unroll
            for (int i = 0; i < 2; i++) {
                afr[i][0] = __float_as_uint(sA[wm + i * 16 + g    ][kk * 8 + t    ]);
                afr[i][1] = __float_as_uint(sA[wm + i * 16 + g + 8][kk * 8 + t    ]);
                afr[i][2] = __float_as_uint(sA[wm + i * 16 + g    ][kk * 8 + t + 4]);
                afr[i][3] = __float_as_uint(sA[wm + i * 16 + g + 8][kk * 8 + t + 4]);
            }
            uint32_t bfr[8][2];
            #pragma unroll
            for (int j = 0; j < 8; j++) {
                bfr[j][0] = __float_as_uint(sB[kk * 8 + t    ][wn + j * 8 + g]);
                bfr[j][1] = __float_as_uint(sB[kk * 8 + t + 4][wn + j * 8 + g]);
            }
            #pragma unroll
            for (int i = 0; i < 2; i++)
                #pragma unroll
                for (int j = 0; j < 8; j++)
                    mma16n8k8(acc[i][j], afr[i], bfr[j]);
        }
        __syncthreads();
    }

    // Epilogue: bias (+ residual), write float2 pairs
    #pragma unroll
    for (int i = 0; i < 2; i++) {
        #pragma unroll
        for (int half = 0; half < 2; half++) {
            int row = m0 + wm + i * 16 + g + half * 8;
            size_t rbase = (size_t)row * HH;
            #pragma unroll
            for (int j = 0; j < 8; j++) {
                int col = n0 + wn + j * 8 + 2 * t;
                float2 o;
                o.x = acc[i][j][half * 2 + 0] + bias[col];
                o.y = acc[i][j][half * 2 + 1] + bias[col + 1];
                if (residual) {
                    float2 rr = *(const float2*)(residual + rbase + col);
                    o.x += rr.x; o.y += rr.y;
                }
                *(float2*)(C + rbase + col) = o;
            }
        }
    }
}

// ===========================================================================
// Flash attention (role swap per reference): S = Q@V^T * 0.25 + mask,
// W = softmax(S), O = W @ K.  (unchanged from passing baseline)
// ===========================================================================
#define TQ 32
#define TK 64

__global__ __launch_bounds__(128) void flash_attn_kernel(
    const float* __restrict__ Q, const float* __restrict__ Kmat,
    const float* __restrict__ Vmat, const float* __restrict__ mask,
    float* __restrict__ Out)
{
    __shared__ float Qs[TQ][64];
    __shared__ float KVs[TK][68];
    __shared__ float Ps[TQ][64];
    __shared__ float maskS[TK];

    const int tid = threadIdx.x;
    const int tn  = tid & 15;
    const int tm  = tid >> 4;
    const int qt  = blockIdx.x;
    const int h   = blockIdx.y;
    const int b   = blockIdx.z;

    const int row0 = b * LL + qt * TQ;
    const int col0 = h * HD;

    for (int t = tid; t < TQ * 16; t += 128) {
        int r = t >> 4, c = (t & 15) * 4;
        *(float4*)&Qs[r][c] = *(const float4*)(Q + (size_t)(row0 + r) * HH + col0 + c);
    }

    float o[4][4];
    float mrow[4], lrow[4];
    #pragma unroll
    for (int i = 0; i < 4; i++) {
        mrow[i] = -1e30f; lrow[i] = 0.f;
        #pragma unroll
        for (int j = 0; j < 4; j++) o[i][j] = 0.f;
    }
    __syncthreads();

    for (int kb = 0; kb < LL / TK; kb++) {
        const int krow0 = b * LL + kb * TK;

        for (int t = tid; t < TK * 16; t += 128) {
            int r = t >> 4, c = (t & 15) * 4;
            *(float4*)&KVs[r][c] = *(const float4*)(Vmat + (size_t)(krow0 + r) * HH + col0 + c);
        }
        if (tid < TK) maskS[tid] = mask[b * LL + kb * TK + tid];
        __syncthreads();

        float s[4][4];
        #pragma unroll
        for (int i = 0; i < 4; i++)
            #pragma unroll
            for (int j = 0; j < 4; j++) s[i][j] = 0.f;

        #pragma unroll
        for (int k = 0; k < 64; k += 4) {
            float4 q4[4], kv4[4];
            #pragma unroll
            for (int i = 0; i < 4; i++) q4[i]  = *(float4*)&Qs[tm * 4 + i][k];
            #pragma unroll
            for (int j = 0; j < 4; j++) kv4[j] = *(float4*)&KVs[tn * 4 + j][k];
            #pragma unroll
            for (int i = 0; i < 4; i++)
                #pragma unroll
                for (int j = 0; j < 4; j++)
                    s[i][j] += q4[i].x * kv4[j].x + q4[i].y * kv4[j].y
                             + q4[i].z * kv4[j].z + q4[i].w * kv4[j].w;
        }

        #pragma unroll
        for (int i = 0; i < 4; i++) {
            #pragma unroll
            for (int j = 0; j < 4; j++)
                s[i][j] = s[i][j] * 0.25f + maskS[tn * 4 + j];

            float mx = fmaxf(fmaxf(s[i][0], s[i][1]), fmaxf(s[i][2], s[i][3]));
            #pragma unroll
            for (int off = 8; off; off >>= 1)
                mx = fmaxf(mx, __shfl_xor_sync(0xffffffffu, mx, off, 16));

            float mnew = fmaxf(mrow[i], mx);
            float corr = __expf(mrow[i] - mnew);
            float rs = 0.f;
            #pragma unroll
            for (int j = 0; j < 4; j++) {
                s[i][j] = __expf(s[i][j] - mnew);
                rs += s[i][j];
            }
            #pragma unroll
            for (int off = 8; off; off >>= 1)
                rs += __shfl_xor_sync(0xffffffffu, rs, off, 16);

            lrow[i] = lrow[i] * corr + rs;
            mrow[i] = mnew;
            #pragma unroll
            for (int j = 0; j < 4; j++) o[i][j] *= corr;

            *(float4*)&Ps[tm * 4 + i][tn * 4] = make_float4(s[i][0], s[i][1], s[i][2], s[i][3]);
        }
        __syncthreads();

        for (int t = tid; t < TK * 16; t += 128) {
            int r = t >> 4, c = (t & 15) * 4;
            *(float4*)&KVs[r][c] = *(const float4*)(Kmat + (size_t)(krow0 + r) * HH + col0 + c);
        }
        __syncthreads();

        #pragma unroll
        for (int c = 0; c < 64; c += 4) {
            float4 p4[4], kk4[4];
            #pragma unroll
            for (int i = 0; i < 4; i++)  p4[i]  = *(float4*)&Ps[tm * 4 + i][c];
            #pragma unroll
            for (int cc = 0; cc < 4; cc++) kk4[cc] = *(float4*)&KVs[c + cc][tn * 4];
            #pragma unroll
            for (int i = 0; i < 4; i++) {
                o[i][0] += p4[i].x * kk4[0].x + p4[i].y * kk4[1].x + p4[i].z * kk4[2].x + p4[i].w * kk4[3].x;
                o[i][1] += p4[i].x * kk4[0].y + p4[i].y * kk4[1].y + p4[i].z * kk4[2].y + p4[i].w * kk4[3].y;
                o[i][2] += p4[i].x * kk4[0].z + p4[i].y * kk4[1].z + p4[i].z * kk4[2].z + p4[i].w * kk4[3].z;
                o[i][3] += p4[i].x * kk4[0].w + p4[i].y * kk4[1].w + p4[i].z * kk4[2].w + p4[i].w * kk4[3].w;
            }
        }
        __syncthreads();
    }

    #pragma unroll
    for (int i = 0; i < 4; i++) {
        float inv = 1.f / lrow[i];
        int row = row0 + tm * 4 + i;
        *(float4*)(Out + (size_t)row * HH + col0 + tn * 4) =
            make_float4(o[i][0] * inv, o[i][1] * inv, o[i][2] * inv, o[i][3] * inv);
    }
}

// ===========================================================================
// Row LayerNorm
// ===========================================================================
__global__ __launch_bounds__(256) void ln_kernel(
    const float* __restrict__ X, const float* __restrict__ gamma,
    const float* __restrict__ beta, float* __restrict__ Y)
{
    __shared__ float sred[8];
    const int r = blockIdx.x;
    const int tid = threadIdx.x;
    const float* x = X + (size_t)r * HH;

    float4 v = *(const float4*)(x + tid * 4);

    float s = v.x + v.y + v.z + v.w;
    #pragma unroll
    for (int off = 16; off; off >>= 1) s += __shfl_xor_sync(0xffffffffu, s, off);
    if ((tid & 31) == 0) sred[tid >> 5] = s;
    __syncthreads();
    float tot = 0.f;
    #pragma unroll
    for (int i = 0; i < 8; i++) tot += sred[i];
    const float mu = tot * (1.f / HH);
    __syncthreads();

    float d0 = v.x - mu, d1 = v.y - mu, d2 = v.z - mu, d3 = v.w - mu;
    float sq = d0 * d0 + d1 * d1 + d2 * d2 + d3 * d3;
    #pragma unroll
    for (int off = 16; off; off >>= 1) sq += __shfl_xor_sync(0xffffffffu, sq, off);
    if ((tid & 31) == 0) sred[tid >> 5] = sq;
    __syncthreads();
    float vtot = 0.f;
    #pragma unroll
    for (int i = 0; i < 8; i++) vtot += sred[i];
    const float var = vtot * (1.f / HH);
    const float inv = rsqrtf(var + LN_EPS);

    float4 g  = *(const float4*)(gamma + tid * 4);
    float4 be = *(const float4*)(beta  + tid * 4);
    *(float4*)(Y + (size_t)r * HH + tid * 4) = make_float4(
        d0 * inv * g.x + be.x, d1 * inv * g.y + be.y,
        d2 * inv * g.z + be.z, d3 * inv * g.w + be.w);
}

// ===========================================================================
// Launch
// ===========================================================================
extern "C" void kernel_launch(void* const* d_in, const int* in_sizes, int n_in,
                              void* d_out, int out_size)
{
    const float* emb   = (const float*)d_in[0];
    const float* mask  = (const float*)d_in[1];
    const float* Wq    = (const float*)d_in[2];
    const float* bq    = (const float*)d_in[3];
    const float* Wk    = (const float*)d_in[4];
    const float* bk    = (const float*)d_in[5];
    const float* Wv    = (const float*)d_in[6];
    const float* bv    = (const float*)d_in[7];
    const float* Wo    = (const float*)d_in[8];
    const float* bo    = (const float*)d_in[9];
    const float* gamma = (const float*)d_in[10];
    const float* beta  = (const float*)d_in[11];
    float* out = (float*)d_out;

    float *Qp, *Kp, *Vp, *Ap, *Pp;
    cudaGetSymbolAddress((void**)&Qp, g_Q);
    cudaGetSymbolAddress((void**)&Kp, g_K);
    cudaGetSymbolAddress((void**)&Vp, g_V);
    cudaGetSymbolAddress((void**)&Ap, g_att);
    cudaGetSymbolAddress((void**)&Pp, g_proj);

    dim3 ggrid(HH / 128, MM / 128);   // (8, 32)
    gemm_mma_kernel<<<ggrid, 256>>>(emb, Wq, bq, nullptr, Qp);
    gemm_mma_kernel<<<ggrid, 256>>>(emb, Wk, bk, nullptr, Kp);
    gemm_mma_kernel<<<ggrid, 256>>>(emb, Wv, bv, nullptr, Vp);

    dim3 agrid(LL / TQ, NH, BB);      // (64, 16, 2)
    flash_attn_kernel<<<agrid, 128>>>(Qp, Kp, Vp, mask, Ap);

    gemm_mma_kernel<<<ggrid, 256>>>(Ap, Wo, bo, emb, Pp);

    ln_kernel<<<MM, 256>>>(Pp, gamma, beta, out);
}

// round 10
// speedup vs baseline: 4.2290x; 3.2203x over previous
#include <cuda_runtime.h>
#include <math.h>
#include <stdint.h>

// Problem constants
#define BB   2
#define LL   2048
#define HH   1024
#define NH   16
#define HD   64
#define MM   (BB*LL)   // 4096 rows
#define LN_EPS 1e-12f

// Scratch (static __device__ globals: allowed; no runtime allocation)
__device__ float g_Q[MM*HH];
__device__ float g_K[MM*HH];
__device__ float g_V[MM*HH];
__device__ float g_att[MM*HH];
__device__ float g_proj[MM*HH];

__device__ __forceinline__ uint32_t cvt_tf32(float x) {
    uint32_t r; asm("cvt.rna.tf32.f32 %0, %1;" : "=r"(r) : "f"(x)); return r;
}
__device__ __forceinline__ float cvt_tf32f(float x) {
    return __uint_as_float(cvt_tf32(x));
}

// Warp-level tensor-core MMA: D[16x8] += A[16x8] * B[8x8], tf32, f32 accum.
__device__ __forceinline__ void mma16n8k8(float c[4], const uint32_t a[4],
                                          const uint32_t b[2]) {
    asm volatile(
        "mma.sync.aligned.m16n8k8.row.col.f32.tf32.tf32.f32 "
        "{%0,%1,%2,%3}, {%4,%5,%6,%7}, {%8,%9}, {%0,%1,%2,%3};"
        : "+f"(c[0]), "+f"(c[1]), "+f"(c[2]), "+f"(c[3])
        : "r"(a[0]), "r"(a[1]), "r"(a[2]), "r"(a[3]),
          "r"(b[0]), "r"(b[1]));
}

// ===========================================================================
// tf32 warp-MMA GEMM: C[M,N] = A[M,K] @ W[K,N] + bias (+ residual)
// CTA tile 128x128, BK=32, 256 threads (8 warps, 4x2), warp tile 32x64.
// ===========================================================================
#define BK 32
#define SA_PAD 36
#define SB_PAD 136

__global__ __launch_bounds__(256) void gemm_mma_kernel(
    const float* __restrict__ A, const float* __restrict__ W,
    const float* __restrict__ bias, const float* __restrict__ residual,
    float* __restrict__ C)
{
    __shared__ float sA[128][SA_PAD];
    __shared__ float sB[BK][SB_PAD];

    const int tid = threadIdx.x;
    const int lid = tid & 31;
    const int wid = tid >> 5;
    const int wm  = (wid >> 1) * 32;
    const int wn  = (wid & 1) * 64;
    const int g   = lid >> 2;
    const int t   = lid & 3;

    const int m0 = blockIdx.y * 128;
    const int n0 = blockIdx.x * 128;

    float acc[2][8][4];
    #pragma unroll
    for (int i = 0; i < 2; i++)
        #pragma unroll
        for (int j = 0; j < 8; j++)
            #pragma unroll
            for (int q = 0; q < 4; q++) acc[i][j][q] = 0.f;

    float4 ra[4], rb[4];

    #pragma unroll
    for (int i = 0; i < 4; i++) {
        int f = i * 256 + tid;
        int r = f >> 3, c = f & 7;
        ra[i] = *(const float4*)(A + (size_t)(m0 + r) * HH + c * 4);
        int rB = f >> 5, cB = f & 31;
        rb[i] = *(const float4*)(W + (size_t)rB * HH + n0 + cB * 4);
    }

    for (int kc = 0; kc < HH / BK; kc++) {
        #pragma unroll
        for (int i = 0; i < 4; i++) {
            int f = i * 256 + tid;
            int r = f >> 3, c = f & 7;
            float* pa = &sA[r][c * 4];
            pa[0] = cvt_tf32f(ra[i].x);
            pa[1] = cvt_tf32f(ra[i].y);
            pa[2] = cvt_tf32f(ra[i].z);
            pa[3] = cvt_tf32f(ra[i].w);
            int rB = f >> 5, cB = f & 31;
            float* pb = &sB[rB][cB * 4];
            pb[0] = cvt_tf32f(rb[i].x);
            pb[1] = cvt_tf32f(rb[i].y);
            pb[2] = cvt_tf32f(rb[i].z);
            pb[3] = cvt_tf32f(rb[i].w);
        }
        __syncthreads();

        if (kc + 1 < HH / BK) {
            int k0 = (kc + 1) * BK;
            #pragma unroll
            for (int i = 0; i < 4; i++) {
                int f = i * 256 + tid;
                int r = f >> 3, c = f & 7;
                ra[i] = *(const float4*)(A + (size_t)(m0 + r) * HH + k0 + c * 4);
                int rB = f >> 5, cB = f & 31;
                rb[i] = *(const float4*)(W + (size_t)(k0 + rB) * HH + n0 + cB * 4);
            }
        }

        #pragma unroll
        for (int kk = 0; kk < 4; kk++) {
            uint32_t afr[2][4];
            #pragma unroll
            for (int i = 0; i < 2; i++) {
                afr[i][0] = __float_as_uint(sA[wm + i * 16 + g    ][kk * 8 + t    ]);
                afr[i][1] = __float_as_uint(sA[wm + i * 16 + g + 8][kk * 8 + t    ]);
                afr[i][2] = __float_as_uint(sA[wm + i * 16 + g    ][kk * 8 + t + 4]);
                afr[i][3] = __float_as_uint(sA[wm + i * 16 + g + 8][kk * 8 + t + 4]);
            }
            uint32_t bfr[8][2];
            #pragma unroll
            for (int j = 0; j < 8; j++) {
                bfr[j][0] = __float_as_uint(sB[kk * 8 + t    ][wn + j * 8 + g]);
                bfr[j][1] = __float_as_uint(sB[kk * 8 + t + 4][wn + j * 8 + g]);
            }
            #pragma unroll
            for (int i = 0; i < 2; i++)
                #pragma unroll
                for (int j = 0; j < 8; j++)
                    mma16n8k8(acc[i][j], afr[i], bfr[j]);
        }
        __syncthreads();
    }

    #pragma unroll
    for (int i = 0; i < 2; i++) {
        #pragma unroll
        for (int half = 0; half < 2; half++) {
            int row = m0 + wm + i * 16 + g + half * 8;
            size_t rbase = (size_t)row * HH;
            #pragma unroll
            for (int j = 0; j < 8; j++) {
                int col = n0 + wn + j * 8 + 2 * t;
                float2 o;
                o.x = acc[i][j][half * 2 + 0] + bias[col];
                o.y = acc[i][j][half * 2 + 1] + bias[col + 1];
                if (residual) {
                    float2 rr = *(const float2*)(residual + rbase + col);
                    o.x += rr.x; o.y += rr.y;
                }
                *(float2*)(C + rbase + col) = o;
            }
        }
    }
}

// ===========================================================================
// Flash attention with warp MMA (role swap per reference):
//   S = Q @ V^T * 0.25 + mask ; W = softmax(S) ; O = W @ K
// CTA: 64 queries x full head (d=64). 128 threads = 4 warps x 16 q-rows.
// Key blocks of 64. Q A-frags live in registers for the whole CTA.
// P aliases the V smem buffer (V dead after S-MMA).
// Bank pads: sVP=68 (bank 4g+t), sK=72 (bank 8t+g) -> conflict-free frag LDS.
// ===========================================================================
#define ATQ 64
#define ATK 64
#define NKB (LL / ATK)   // 32

__global__ __launch_bounds__(128) void flash_attn_mma_kernel(
    const float* __restrict__ Q, const float* __restrict__ Kmat,
    const float* __restrict__ Vmat, const float* __restrict__ mask,
    float* __restrict__ Out)
{
    __shared__ float sVP[ATK][68];   // V tile, then P tile (aliased)
    __shared__ float sK[ATK][72];    // K tile
    __shared__ float maskS[ATK];

    const int tid  = threadIdx.x;
    const int lid  = tid & 31;
    const int wid  = tid >> 5;
    const int g    = lid >> 2;       // 0..7
    const int t    = lid & 3;        // 0..3
    const int wrow = wid * 16;

    const int qt = blockIdx.x;
    const int h  = blockIdx.y;
    const int b  = blockIdx.z;
    const int row0 = b * LL + qt * ATQ;
    const int col0 = h * HD;

    // ---- Stage Q through sVP, build A-fragments in registers ----
    #pragma unroll
    for (int i = 0; i < 8; i++) {
        int idx = i * 128 + tid;
        int r = idx >> 4, c = (idx & 15) * 4;
        float4 v = *(const float4*)(Q + (size_t)(row0 + r) * HH + col0 + c);
        float* p = &sVP[r][c];
        p[0] = cvt_tf32f(v.x); p[1] = cvt_tf32f(v.y);
        p[2] = cvt_tf32f(v.z); p[3] = cvt_tf32f(v.w);
    }
    __syncthreads();
    uint32_t qf[8][4];
    #pragma unroll
    for (int kk = 0; kk < 8; kk++) {
        qf[kk][0] = __float_as_uint(sVP[wrow + g    ][kk * 8 + t    ]);
        qf[kk][1] = __float_as_uint(sVP[wrow + g + 8][kk * 8 + t    ]);
        qf[kk][2] = __float_as_uint(sVP[wrow + g    ][kk * 8 + t + 4]);
        qf[kk][3] = __float_as_uint(sVP[wrow + g + 8][kk * 8 + t + 4]);
    }
    __syncthreads();

    float of[8][4];
    #pragma unroll
    for (int j = 0; j < 8; j++)
        #pragma unroll
        for (int q = 0; q < 4; q++) of[j][q] = 0.f;
    float mrow[2] = {-1e30f, -1e30f};
    float lrow[2] = {0.f, 0.f};

    // Preload key block 0 (V and K) into registers
    float4 vreg[8], kreg[8];
    {
        const int kr0 = b * LL;
        #pragma unroll
        for (int i = 0; i < 8; i++) {
            int idx = i * 128 + tid;
            int r = idx >> 4, c = (idx & 15) * 4;
            vreg[i] = *(const float4*)(Vmat + (size_t)(kr0 + r) * HH + col0 + c);
            kreg[i] = *(const float4*)(Kmat + (size_t)(kr0 + r) * HH + col0 + c);
        }
    }

    for (int kb = 0; kb < NKB; kb++) {
        // ---- Store staged V and K tiles to smem (tf32) ----
        #pragma unroll
        for (int i = 0; i < 8; i++) {
            int idx = i * 128 + tid;
            int r = idx >> 4, c = (idx & 15) * 4;
            float* pv = &sVP[r][c];
            pv[0] = cvt_tf32f(vreg[i].x); pv[1] = cvt_tf32f(vreg[i].y);
            pv[2] = cvt_tf32f(vreg[i].z); pv[3] = cvt_tf32f(vreg[i].w);
            float* pk = &sK[r][c];
            pk[0] = cvt_tf32f(kreg[i].x); pk[1] = cvt_tf32f(kreg[i].y);
            pk[2] = cvt_tf32f(kreg[i].z); pk[3] = cvt_tf32f(kreg[i].w);
        }
        if (tid < ATK) maskS[tid] = mask[b * LL + kb * ATK + tid];
        __syncthreads();                           // (A)

        // ---- Prefetch next key block ----
        if (kb + 1 < NKB) {
            const int krn = b * LL + (kb + 1) * ATK;
            #pragma unroll
            for (int i = 0; i < 8; i++) {
                int idx = i * 128 + tid;
                int r = idx >> 4, c = (idx & 15) * 4;
                vreg[i] = *(const float4*)(Vmat + (size_t)(krn + r) * HH + col0 + c);
                kreg[i] = *(const float4*)(Kmat + (size_t)(krn + r) * HH + col0 + c);
            }
        }

        // ---- S = Q @ V^T (64 MMAs) ----
        float sf[8][4];
        #pragma unroll
        for (int j = 0; j < 8; j++)
            #pragma unroll
            for (int q = 0; q < 4; q++) sf[j][q] = 0.f;

        #pragma unroll
        for (int kk = 0; kk < 8; kk++) {
            uint32_t bfr[8][2];
            #pragma unroll
            for (int jn = 0; jn < 8; jn++) {
                bfr[jn][0] = __float_as_uint(sVP[jn * 8 + g][kk * 8 + t    ]);
                bfr[jn][1] = __float_as_uint(sVP[jn * 8 + g][kk * 8 + t + 4]);
            }
            #pragma unroll
            for (int jn = 0; jn < 8; jn++)
                mma16n8k8(sf[jn], qf[kk], bfr[jn]);
        }

        // ---- scale + mask + online softmax on fragments ----
        #pragma unroll
        for (int jn = 0; jn < 8; jn++) {
            float mk0 = maskS[jn * 8 + 2 * t];
            float mk1 = maskS[jn * 8 + 2 * t + 1];
            sf[jn][0] = sf[jn][0] * 0.25f + mk0;
            sf[jn][1] = sf[jn][1] * 0.25f + mk1;
            sf[jn][2] = sf[jn][2] * 0.25f + mk0;
            sf[jn][3] = sf[jn][3] * 0.25f + mk1;
        }
        float corr[2];
        #pragma unroll
        for (int hf = 0; hf < 2; hf++) {
            float mx = -1e30f;
            #pragma unroll
            for (int jn = 0; jn < 8; jn++)
                mx = fmaxf(mx, fmaxf(sf[jn][hf * 2], sf[jn][hf * 2 + 1]));
            mx = fmaxf(mx, __shfl_xor_sync(0xffffffffu, mx, 1));
            mx = fmaxf(mx, __shfl_xor_sync(0xffffffffu, mx, 2));

            float mnew = fmaxf(mrow[hf], mx);
            corr[hf] = __expf(mrow[hf] - mnew);
            float rs = 0.f;
            #pragma unroll
            for (int jn = 0; jn < 8; jn++) {
                sf[jn][hf * 2]     = __expf(sf[jn][hf * 2]     - mnew);
                sf[jn][hf * 2 + 1] = __expf(sf[jn][hf * 2 + 1] - mnew);
                rs += sf[jn][hf * 2] + sf[jn][hf * 2 + 1];
            }
            rs += __shfl_xor_sync(0xffffffffu, rs, 1);
            rs += __shfl_xor_sync(0xffffffffu, rs, 2);
            lrow[hf] = lrow[hf] * corr[hf] + rs;
            mrow[hf] = mnew;
            #pragma unroll
            for (int jn = 0; jn < 8; jn++) {
                of[jn][hf * 2]     *= corr[hf];
                of[jn][hf * 2 + 1] *= corr[hf];
            }
        }
        __syncthreads();                           // (D) all warps done reading sVP as V

        // ---- Write P into sVP (own warp rows only) ----
        #pragma unroll
        for (int jn = 0; jn < 8; jn++) {
            float2 p0 = make_float2(cvt_tf32f(sf[jn][0]), cvt_tf32f(sf[jn][1]));
            float2 p1 = make_float2(cvt_tf32f(sf[jn][2]), cvt_tf32f(sf[jn][3]));
            *(float2*)&sVP[wrow + g    ][jn * 8 + 2 * t] = p0;
            *(float2*)&sVP[wrow + g + 8][jn * 8 + 2 * t] = p1;
        }
        __syncwarp();

        // ---- O += P @ K (64 MMAs) ----
        #pragma unroll
        for (int kk = 0; kk < 8; kk++) {
            uint32_t afr[4];
            afr[0] = __float_as_uint(sVP[wrow + g    ][kk * 8 + t    ]);
            afr[1] = __float_as_uint(sVP[wrow + g + 8][kk * 8 + t    ]);
            afr[2] = __float_as_uint(sVP[wrow + g    ][kk * 8 + t + 4]);
            afr[3] = __float_as_uint(sVP[wrow + g + 8][kk * 8 + t + 4]);
            uint32_t bfr[8][2];
            #pragma unroll
            for (int jd = 0; jd < 8; jd++) {
                bfr[jd][0] = __float_as_uint(sK[kk * 8 + t    ][jd * 8 + g]);
                bfr[jd][1] = __float_as_uint(sK[kk * 8 + t + 4][jd * 8 + g]);
            }
            #pragma unroll
            for (int jd = 0; jd < 8; jd++)
                mma16n8k8(of[jd], afr, bfr[jd]);
        }
        __syncthreads();                           // (C) before next block overwrites smem
    }

    // ---- Normalize and write ----
    float inv0 = 1.f / lrow[0];
    float inv1 = 1.f / lrow[1];
    const size_t r0 = (size_t)(row0 + wrow + g) * HH + col0;
    const size_t r1 = (size_t)(row0 + wrow + g + 8) * HH + col0;
    #pragma unroll
    for (int jd = 0; jd < 8; jd++) {
        int col = jd * 8 + 2 * t;
        *(float2*)(Out + r0 + col) = make_float2(of[jd][0] * inv0, of[jd][1] * inv0);
        *(float2*)(Out + r1 + col) = make_float2(of[jd][2] * inv1, of[jd][3] * inv1);
    }
}

// ===========================================================================
// Row LayerNorm
// ===========================================================================
__global__ __launch_bounds__(256) void ln_kernel(
    const float* __restrict__ X, const float* __restrict__ gamma,
    const float* __restrict__ beta, float* __restrict__ Y)
{
    __shared__ float sred[8];
    const int r = blockIdx.x;
    const int tid = threadIdx.x;
    const float* x = X + (size_t)r * HH;

    float4 v = *(const float4*)(x + tid * 4);

    float s = v.x + v.y + v.z + v.w;
    #pragma unroll
    for (int off = 16; off; off >>= 1) s += __shfl_xor_sync(0xffffffffu, s, off);
    if ((tid & 31) == 0) sred[tid >> 5] = s;
    __syncthreads();
    float tot = 0.f;
    #pragma unroll
    for (int i = 0; i < 8; i++) tot += sred[i];
    const float mu = tot * (1.f / HH);
    __syncthreads();

    float d0 = v.x - mu, d1 = v.y - mu, d2 = v.z - mu, d3 = v.w - mu;
    float sq = d0 * d0 + d1 * d1 + d2 * d2 + d3 * d3;
    #pragma unroll
    for (int off = 16; off; off >>= 1) sq += __shfl_xor_sync(0xffffffffu, sq, off);
    if ((tid & 31) == 0) sred[tid >> 5] = sq;
    __syncthreads();
    float vtot = 0.f;
    #pragma unroll
    for (int i = 0; i < 8; i++) vtot += sred[i];
    const float var = vtot * (1.f / HH);
    const float inv = rsqrtf(var + LN_EPS);

    float4 g  = *(const float4*)(gamma + tid * 4);
    float4 be = *(const float4*)(beta  + tid * 4);
    *(float4*)(Y + (size_t)r * HH + tid * 4) = make_float4(
        d0 * inv * g.x + be.x, d1 * inv * g.y + be.y,
        d2 * inv * g.z + be.z, d3 * inv * g.w + be.w);
}

// ===========================================================================
// Launch
// ===========================================================================
extern "C" void kernel_launch(void* const* d_in, const int* in_sizes, int n_in,
                              void* d_out, int out_size)
{
    const float* emb   = (const float*)d_in[0];
    const float* mask  = (const float*)d_in[1];
    const float* Wq    = (const float*)d_in[2];
    const float* bq    = (const float*)d_in[3];
    const float* Wk    = (const float*)d_in[4];
    const float* bk    = (const float*)d_in[5];
    const float* Wv    = (const float*)d_in[6];
    const float* bv    = (const float*)d_in[7];
    const float* Wo    = (const float*)d_in[8];
    const float* bo    = (const float*)d_in[9];
    const float* gamma = (const float*)d_in[10];
    const float* beta  = (const float*)d_in[11];
    float* out = (float*)d_out;

    float *Qp, *Kp, *Vp, *Ap, *Pp;
    cudaGetSymbolAddress((void**)&Qp, g_Q);
    cudaGetSymbolAddress((void**)&Kp, g_K);
    cudaGetSymbolAddress((void**)&Vp, g_V);
    cudaGetSymbolAddress((void**)&Ap, g_att);
    cudaGetSymbolAddress((void**)&Pp, g_proj);

    dim3 ggrid(HH / 128, MM / 128);   // (8, 32)
    gemm_mma_kernel<<<ggrid, 256>>>(emb, Wq, bq, nullptr, Qp);
    gemm_mma_kernel<<<ggrid, 256>>>(emb, Wk, bk, nullptr, Kp);
    gemm_mma_kernel<<<ggrid, 256>>>(emb, Wv, bv, nullptr, Vp);

    dim3 agrid(LL / ATQ, NH, BB);     // (32, 16, 2)
    flash_attn_mma_kernel<<<agrid, 128>>>(Qp, Kp, Vp, mask, Ap);

    gemm_mma_kernel<<<ggrid, 256>>>(Ap, Wo, bo, emb, Pp);

    ln_kernel<<<MM, 256>>>(Pp, gamma, beta, out);
}